// round 6
// baseline (speedup 1.0000x reference)
#include <cuda_runtime.h>

#define DD 128
#define TOX 28          // outputs per warp in x (lanes 2..29)
#define TOY 16          // output rows per tile (warp w owns rows 2w, 2w+1)
#define HYR 20          // halo rows
#define NT 256
#define ZCHUNK 32

__device__ double g_acc;

__global__ void k_zero() { g_acc = 0.0; }

#define FULLM 0xFFFFFFFFu
// x-conv of a register field via shuffles (valid at lanes 2..29)
#define XC(dst, f)                                              \
    {                                                           \
        float m2 = __shfl_up_sync(FULLM, (f), 2);               \
        float m1 = __shfl_up_sync(FULLM, (f), 1);               \
        float q1 = __shfl_down_sync(FULLM, (f), 1);             \
        float q2 = __shfl_down_sync(FULLM, (f), 2);             \
        dst = W0 * (m2 + q2) + W1 * (m1 + q1) + W2 * (f);       \
    }
// rotating z-accumulator update, U compile-time. After this, acc[(U+3)%5]
// holds the COMPLETED z-conv for output depth z0+zi-4.
#define ZUPD(acc, Pv, U)                                        \
    acc[(U + 3) % 5] += W0 * (Pv);                              \
    acc[(U + 4) % 5] += W1 * (Pv);                              \
    acc[(U) % 5]     += W2 * (Pv);                              \
    acc[(U + 1) % 5] += W1 * (Pv);                              \
    acc[(U + 2) % 5]  = W0 * (Pv);

__global__ void __launch_bounds__(NT, 2) k_ssim(const float* __restrict__ x,
                                                const float* __restrict__ y) {
    constexpr float W0 = 0.120078385f;
    constexpr float W1 = 0.233880764f;
    constexpr float W2 = 0.292081722f;
    constexpr float C1 = 1e-4f;
    constexpr float C2 = 9e-4f;

    __shared__ float4 sF[2][HYR][32];    // {u, v, u^2+v^2, u*v}, double-buffered
    __shared__ float sred[NT / 32];

    const int t = threadIdx.x;
    const int lane = t & 31, w = t >> 5;
    const int x0 = blockIdx.x * TOX;
    const int gx = x0 + lane - 2;
    const int h0 = blockIdx.y * TOY;
    const int nc = blockIdx.z >> 2;
    const int z0 = (blockIdx.z & 3) * ZCHUNK;
    const int base = nc << 21;

    // halo rows owned by this warp: w, w+8, (w+16 if w<4)
    const int gh0 = h0 + w - 2;
    const int gh1 = h0 + w + 6;
    const int gh2 = h0 + w + 14;
    const bool okx = ((unsigned)gx < DD);
    const bool ok0 = okx && ((unsigned)gh0 < DD);
    const bool ok1 = okx && ((unsigned)gh1 < DD);
    const bool ok2 = okx && ((unsigned)gh2 < DD) && (w < 4);
    const int off0 = base + gh0 * DD + gx;
    const int off1 = base + gh1 * DD + gx;
    const int off2 = base + gh2 * DD + gx;
    const bool outok = (lane >= 2) && (lane <= 29) && okx;

    // z-accumulators: 2 rows x 4 fields x 5 slots
    float aA0[5], aA1[5], aA2[5], aA3[5];
    float aB0[5], aB1[5], aB2[5], aB3[5];
#pragma unroll
    for (int j = 0; j < 5; ++j) {
        aA0[j] = aA1[j] = aA2[j] = aA3[j] = 0.f;
        aB0[j] = aB1[j] = aB2[j] = aB3[j] = 0.f;
    }

    float tsum = 0.f;

    // prologue prefetch: plane zi=0 -> zin = z0-2
    float px0 = 0.f, py0 = 0.f, px1 = 0.f, py1 = 0.f, px2 = 0.f, py2 = 0.f;
    {
        int zin = z0 - 2;
        if ((unsigned)zin < DD) {
            int zo = zin << 14;
            if (ok0) { px0 = x[off0 + zo]; py0 = y[off0 + zo]; }
            if (ok1) { px1 = x[off1 + zo]; py1 = y[off1 + zo]; }
            if (ok2) { px2 = x[off2 + zo]; py2 = y[off2 + zo]; }
        }
    }

#pragma unroll 1
    for (int zb = 0; zb < 8; ++zb) {
#pragma unroll
        for (int uu = 0; uu < 5; ++uu) {
            const int zi = zb * 5 + uu;
            if (zi < 36) {
                const int zin = z0 + zi - 2;
                const bool live = ((unsigned)zin < DD);
                const int b = zi & 1;
                if (live) {
                    // commit prefetched plane
                    {
                        float u = ok0 ? px0 * 0.5f + 0.5f : 0.f;
                        float v = ok0 ? py0 * 0.5f + 0.5f : 0.f;
                        sF[b][w][lane] = make_float4(u, v, u * u + v * v, u * v);
                    }
                    {
                        float u = ok1 ? px1 * 0.5f + 0.5f : 0.f;
                        float v = ok1 ? py1 * 0.5f + 0.5f : 0.f;
                        sF[b][w + 8][lane] = make_float4(u, v, u * u + v * v, u * v);
                    }
                    if (w < 4) {
                        float u = ok2 ? px2 * 0.5f + 0.5f : 0.f;
                        float v = ok2 ? py2 * 0.5f + 0.5f : 0.f;
                        sF[b][w + 16][lane] = make_float4(u, v, u * u + v * v, u * v);
                    }
                }
                // prefetch next plane (flies across barrier + compute)
                {
                    int nz = zin + 1;
                    bool ln = ((unsigned)nz < DD) && (zi + 1 < 36);
                    int zo = nz << 14;
                    px0 = (ln && ok0) ? x[off0 + zo] : 0.f;
                    py0 = (ln && ok0) ? y[off0 + zo] : 0.f;
                    px1 = (ln && ok1) ? x[off1 + zo] : 0.f;
                    py1 = (ln && ok1) ? y[off1 + zo] : 0.f;
                    px2 = (ln && ok2) ? x[off2 + zo] : 0.f;
                    py2 = (ln && ok2) ? y[off2 + zo] : 0.f;
                }
                float PA0 = 0.f, PA1 = 0.f, PA2 = 0.f, PA3 = 0.f;
                float PB0 = 0.f, PB1 = 0.f, PB2 = 0.f, PB3 = 0.f;
                if (live) {
                    __syncthreads();
                    // y-conv: output rows 2w, 2w+1 share 6 tap rows
                    const int r = 2 * w;
                    float4 t0 = sF[b][r + 0][lane];
                    float4 t1 = sF[b][r + 1][lane];
                    float4 t2 = sF[b][r + 2][lane];
                    float4 t3 = sF[b][r + 3][lane];
                    float4 t4 = sF[b][r + 4][lane];
                    float4 t5 = sF[b][r + 5][lane];
                    float Ay0 = W0 * (t0.x + t4.x) + W1 * (t1.x + t3.x) + W2 * t2.x;
                    float Ay1 = W0 * (t0.y + t4.y) + W1 * (t1.y + t3.y) + W2 * t2.y;
                    float Ay2 = W0 * (t0.z + t4.z) + W1 * (t1.z + t3.z) + W2 * t2.z;
                    float Ay3 = W0 * (t0.w + t4.w) + W1 * (t1.w + t3.w) + W2 * t2.w;
                    float By0 = W0 * (t1.x + t5.x) + W1 * (t2.x + t4.x) + W2 * t3.x;
                    float By1 = W0 * (t1.y + t5.y) + W1 * (t2.y + t4.y) + W2 * t3.y;
                    float By2 = W0 * (t1.z + t5.z) + W1 * (t2.z + t4.z) + W2 * t3.z;
                    float By3 = W0 * (t1.w + t5.w) + W1 * (t2.w + t4.w) + W2 * t3.w;
                    // x-conv via shuffles
                    XC(PA0, Ay0); XC(PA1, Ay1); XC(PA2, Ay2); XC(PA3, Ay3);
                    XC(PB0, By0); XC(PB1, By1); XC(PB2, By2); XC(PB3, By3);
                }
                // z-accumulate (static rotation)
                ZUPD(aA0, PA0, uu); ZUPD(aA1, PA1, uu);
                ZUPD(aA2, PA2, uu); ZUPD(aA3, PA3, uu);
                ZUPD(aB0, PB0, uu); ZUPD(aB1, PB1, uu);
                ZUPD(aB2, PB2, uu); ZUPD(aB3, PB3, uu);
                // consume completed output depth z0+zi-4 at slot (uu+3)%5
                if (zi >= 4) {
                    constexpr int S0 = 0;  // placeholder for readability
                    (void)S0;
                    {
                        float A = aA0[(uu + 3) % 5], B = aA1[(uu + 3) % 5];
                        float Q = aA2[(uu + 3) % 5], P = aA3[(uu + 3) % 5];
                        float ab = A * B;
                        float a2b2 = A * A + B * B;
                        float num = (2.f * ab + C1) * (2.f * (P - ab) + C2);
                        float den = (a2b2 + C1) * ((Q - a2b2) + C2);
                        float v = __fdividef(num, den);
                        if (outok) tsum += v;
                    }
                    {
                        float A = aB0[(uu + 3) % 5], B = aB1[(uu + 3) % 5];
                        float Q = aB2[(uu + 3) % 5], P = aB3[(uu + 3) % 5];
                        float ab = A * B;
                        float a2b2 = A * A + B * B;
                        float num = (2.f * ab + C1) * (2.f * (P - ab) + C2);
                        float den = (a2b2 + C1) * ((Q - a2b2) + C2);
                        float v = __fdividef(num, den);
                        if (outok) tsum += v;
                    }
                }
            }
        }
    }

    // ---- block reduction ----
#pragma unroll
    for (int off = 16; off; off >>= 1)
        tsum += __shfl_xor_sync(FULLM, tsum, off);
    if (lane == 0) sred[w] = tsum;
    __syncthreads();
    if (t < NT / 32) {
        float v2 = sred[t];
#pragma unroll
        for (int off = NT / 64; off; off >>= 1)
            v2 += __shfl_xor_sync(0x000000FFu, v2, off);
        if (t == 0) atomicAdd(&g_acc, (double)v2);
    }
}

__global__ void k_final(float* out) {
    out[0] = (float)(g_acc * (1.0 / 16777216.0));
}

extern "C" void kernel_launch(void* const* d_in, const int* in_sizes, int n_in,
                              void* d_out, int out_size) {
    const float* x = (const float*)d_in[0];
    const float* y = (const float*)d_in[1];
    k_zero<<<1, 1>>>();
    dim3 grid((DD + TOX - 1) / TOX, DD / TOY, 8 * 4);  // (5, 8, 32) = 1280 CTAs
    dim3 blk(NT);
    k_ssim<<<grid, blk>>>(x, y);
    k_final<<<1, 1>>>((float*)d_out);
}

// round 7
// speedup vs baseline: 1.0022x; 1.0022x over previous
#include <cuda_runtime.h>

#define DD 128
#define TOX 28          // outputs per warp in x (lanes 2..29)
#define TOY 16          // output rows per tile (warp w owns rows 2w, 2w+1)
#define HYR 20          // halo rows
#define NT 256
#define ZCHUNK 32

__device__ double g_acc;

__global__ void k_zero() { g_acc = 0.0; }

#define FULLM 0xFFFFFFFFu
// x-conv of a register field via shuffles (valid at lanes 2..29)
#define XC(dst, f)                                              \
    {                                                           \
        float m2 = __shfl_up_sync(FULLM, (f), 2);               \
        float m1 = __shfl_up_sync(FULLM, (f), 1);               \
        float q1 = __shfl_down_sync(FULLM, (f), 1);             \
        float q2 = __shfl_down_sync(FULLM, (f), 2);             \
        dst = W0 * (m2 + q2) + W1 * (m1 + q1) + W2 * (f);       \
    }
// rotating z-accumulator update, U compile-time. After this, acc[(U+3)%5]
// holds the COMPLETED z-conv for output depth z0+zi-4.
#define ZUPD(acc, Pv, U)                                        \
    acc[(U + 3) % 5] += W0 * (Pv);                              \
    acc[(U + 4) % 5] += W1 * (Pv);                              \
    acc[(U) % 5]     += W2 * (Pv);                              \
    acc[(U + 1) % 5] += W1 * (Pv);                              \
    acc[(U + 2) % 5]  = W0 * (Pv);

__global__ void __launch_bounds__(NT, 2) k_ssim(const float* __restrict__ x,
                                                const float* __restrict__ y) {
    constexpr float W0 = 0.120078385f;
    constexpr float W1 = 0.233880764f;
    constexpr float W2 = 0.292081722f;
    constexpr float C1 = 1e-4f;
    constexpr float C2 = 9e-4f;

    __shared__ float4 sF[2][HYR][32];    // {u, v, u^2+v^2, u*v}, double-buffered
    __shared__ float sred[NT / 32];

    const int t = threadIdx.x;
    const int lane = t & 31, w = t >> 5;
    const int x0 = blockIdx.x * TOX;
    const int gx = x0 + lane - 2;
    const int h0 = blockIdx.y * TOY;
    const int nc = blockIdx.z >> 2;
    const int z0 = (blockIdx.z & 3) * ZCHUNK;
    const int base = nc << 21;

    // halo rows owned by this warp: w, w+8, (w+16 if w<4)
    const int gh0 = h0 + w - 2;
    const int gh1 = h0 + w + 6;
    const int gh2 = h0 + w + 14;
    const bool okx = ((unsigned)gx < DD);
    const bool ok0 = okx && ((unsigned)gh0 < DD);
    const bool ok1 = okx && ((unsigned)gh1 < DD);
    const bool ok2 = okx && ((unsigned)gh2 < DD) && (w < 4);
    const int off0 = base + gh0 * DD + gx;
    const int off1 = base + gh1 * DD + gx;
    const int off2 = base + gh2 * DD + gx;
    const bool outok = (lane >= 2) && (lane <= 29) && okx;

    // z-accumulators: 2 rows x 4 fields x 5 slots
    float aA0[5], aA1[5], aA2[5], aA3[5];
    float aB0[5], aB1[5], aB2[5], aB3[5];
#pragma unroll
    for (int j = 0; j < 5; ++j) {
        aA0[j] = aA1[j] = aA2[j] = aA3[j] = 0.f;
        aB0[j] = aB1[j] = aB2[j] = aB3[j] = 0.f;
    }

    float tsum = 0.f;

    // prologue prefetch: plane zi=0 -> zin = z0-2
    float px0 = 0.f, py0 = 0.f, px1 = 0.f, py1 = 0.f, px2 = 0.f, py2 = 0.f;
    {
        int zin = z0 - 2;
        if ((unsigned)zin < DD) {
            int zo = zin << 14;
            if (ok0) { px0 = x[off0 + zo]; py0 = y[off0 + zo]; }
            if (ok1) { px1 = x[off1 + zo]; py1 = y[off1 + zo]; }
            if (ok2) { px2 = x[off2 + zo]; py2 = y[off2 + zo]; }
        }
    }

#pragma unroll 1
    for (int zb = 0; zb < 8; ++zb) {
#pragma unroll
        for (int uu = 0; uu < 5; ++uu) {
            const int zi = zb * 5 + uu;
            if (zi < 36) {
                const int zin = z0 + zi - 2;
                const bool live = ((unsigned)zin < DD);
                const int b = zi & 1;
                if (live) {
                    // commit prefetched plane
                    {
                        float u = ok0 ? px0 * 0.5f + 0.5f : 0.f;
                        float v = ok0 ? py0 * 0.5f + 0.5f : 0.f;
                        sF[b][w][lane] = make_float4(u, v, u * u + v * v, u * v);
                    }
                    {
                        float u = ok1 ? px1 * 0.5f + 0.5f : 0.f;
                        float v = ok1 ? py1 * 0.5f + 0.5f : 0.f;
                        sF[b][w + 8][lane] = make_float4(u, v, u * u + v * v, u * v);
                    }
                    if (w < 4) {
                        float u = ok2 ? px2 * 0.5f + 0.5f : 0.f;
                        float v = ok2 ? py2 * 0.5f + 0.5f : 0.f;
                        sF[b][w + 16][lane] = make_float4(u, v, u * u + v * v, u * v);
                    }
                }
                // prefetch next plane (flies across barrier + compute)
                {
                    int nz = zin + 1;
                    bool ln = ((unsigned)nz < DD) && (zi + 1 < 36);
                    int zo = nz << 14;
                    px0 = (ln && ok0) ? x[off0 + zo] : 0.f;
                    py0 = (ln && ok0) ? y[off0 + zo] : 0.f;
                    px1 = (ln && ok1) ? x[off1 + zo] : 0.f;
                    py1 = (ln && ok1) ? y[off1 + zo] : 0.f;
                    px2 = (ln && ok2) ? x[off2 + zo] : 0.f;
                    py2 = (ln && ok2) ? y[off2 + zo] : 0.f;
                }
                float PA0 = 0.f, PA1 = 0.f, PA2 = 0.f, PA3 = 0.f;
                float PB0 = 0.f, PB1 = 0.f, PB2 = 0.f, PB3 = 0.f;
                if (live) {
                    __syncthreads();
                    // y-conv: output rows 2w, 2w+1 share 6 tap rows
                    const int r = 2 * w;
                    float4 t0 = sF[b][r + 0][lane];
                    float4 t1 = sF[b][r + 1][lane];
                    float4 t2 = sF[b][r + 2][lane];
                    float4 t3 = sF[b][r + 3][lane];
                    float4 t4 = sF[b][r + 4][lane];
                    float4 t5 = sF[b][r + 5][lane];
                    float Ay0 = W0 * (t0.x + t4.x) + W1 * (t1.x + t3.x) + W2 * t2.x;
                    float Ay1 = W0 * (t0.y + t4.y) + W1 * (t1.y + t3.y) + W2 * t2.y;
                    float Ay2 = W0 * (t0.z + t4.z) + W1 * (t1.z + t3.z) + W2 * t2.z;
                    float Ay3 = W0 * (t0.w + t4.w) + W1 * (t1.w + t3.w) + W2 * t2.w;
                    float By0 = W0 * (t1.x + t5.x) + W1 * (t2.x + t4.x) + W2 * t3.x;
                    float By1 = W0 * (t1.y + t5.y) + W1 * (t2.y + t4.y) + W2 * t3.y;
                    float By2 = W0 * (t1.z + t5.z) + W1 * (t2.z + t4.z) + W2 * t3.z;
                    float By3 = W0 * (t1.w + t5.w) + W1 * (t2.w + t4.w) + W2 * t3.w;
                    // x-conv via shuffles
                    XC(PA0, Ay0); XC(PA1, Ay1); XC(PA2, Ay2); XC(PA3, Ay3);
                    XC(PB0, By0); XC(PB1, By1); XC(PB2, By2); XC(PB3, By3);
                }
                // z-accumulate (static rotation)
                ZUPD(aA0, PA0, uu); ZUPD(aA1, PA1, uu);
                ZUPD(aA2, PA2, uu); ZUPD(aA3, PA3, uu);
                ZUPD(aB0, PB0, uu); ZUPD(aB1, PB1, uu);
                ZUPD(aB2, PB2, uu); ZUPD(aB3, PB3, uu);
                // consume completed output depth z0+zi-4 at slot (uu+3)%5
                if (zi >= 4) {
                    constexpr int S0 = 0;  // placeholder for readability
                    (void)S0;
                    {
                        float A = aA0[(uu + 3) % 5], B = aA1[(uu + 3) % 5];
                        float Q = aA2[(uu + 3) % 5], P = aA3[(uu + 3) % 5];
                        float ab = A * B;
                        float a2b2 = A * A + B * B;
                        float num = (2.f * ab + C1) * (2.f * (P - ab) + C2);
                        float den = (a2b2 + C1) * ((Q - a2b2) + C2);
                        float v = __fdividef(num, den);
                        if (outok) tsum += v;
                    }
                    {
                        float A = aB0[(uu + 3) % 5], B = aB1[(uu + 3) % 5];
                        float Q = aB2[(uu + 3) % 5], P = aB3[(uu + 3) % 5];
                        float ab = A * B;
                        float a2b2 = A * A + B * B;
                        float num = (2.f * ab + C1) * (2.f * (P - ab) + C2);
                        float den = (a2b2 + C1) * ((Q - a2b2) + C2);
                        float v = __fdividef(num, den);
                        if (outok) tsum += v;
                    }
                }
            }
        }
    }

    // ---- block reduction ----
#pragma unroll
    for (int off = 16; off; off >>= 1)
        tsum += __shfl_xor_sync(FULLM, tsum, off);
    if (lane == 0) sred[w] = tsum;
    __syncthreads();
    if (t < NT / 32) {
        float v2 = sred[t];
#pragma unroll
        for (int off = NT / 64; off; off >>= 1)
            v2 += __shfl_xor_sync(0x000000FFu, v2, off);
        if (t == 0) atomicAdd(&g_acc, (double)v2);
    }
}

__global__ void k_final(float* out) {
    out[0] = (float)(g_acc * (1.0 / 16777216.0));
}

extern "C" void kernel_launch(void* const* d_in, const int* in_sizes, int n_in,
                              void* d_out, int out_size) {
    const float* x = (const float*)d_in[0];
    const float* y = (const float*)d_in[1];
    k_zero<<<1, 1>>>();
    dim3 grid((DD + TOX - 1) / TOX, DD / TOY, 8 * 4);  // (5, 8, 32) = 1280 CTAs
    dim3 blk(NT);
    k_ssim<<<grid, blk>>>(x, y);
    k_final<<<1, 1>>>((float*)d_out);
}